// round 9
// baseline (speedup 1.0000x reference)
#include <cuda_runtime.h>
#include <cuda_bf16.h>
#include <cstdint>

// Degree-2 Taylor attention with RPE via warp-level mma.sync (bf16 x3-split)
// + rolling band ring + in-register S (accumulator->A-fragment reuse).
// BI=128, BJ=64, 512 threads (16 warps), grid 8 x 16 = 128 CTAs, 1 CTA/SM.

constexpr int NSEQ = 1024, BI = 128, BJ = 64, NT = NSEQ / BJ;
constexpr int RSTR = 200;   // ring stride in floats

// smem byte offsets
constexpr int Q_HI = 0,      Q_LO = 16384;   // 128x64 bf16
constexpr int K_HI = 32768,  K_LO = 40960;   // 64x64
constexpr int R_HI = 49152,  R_LO = 57344;   // 64 rpe rows
constexpr int V_HI = 65536,  V_LO = 73728;   // 64x64 natural
constexpr int RING = 81920;                  // 128 x 200 f32 ring
constexpr int DEN  = RING + 128 * RSTR * 4;  // 184320
constexpr int SMEM_BYTES = DEN + 512;        // 184832
// epilogue O buffer aliases [0, 34816) (Q/K dead after loop), stride 68 floats

#define SWZ(o) ((o) ^ ((((o) >> 7) & 7) << 4))

__device__ __forceinline__ uint32_t smem_u32(const void* p) {
    uint32_t a;
    asm("{ .reg .u64 t; cvta.to.shared.u64 t, %1; cvt.u32.u64 %0, t; }"
        : "=r"(a) : "l"(p));
    return a;
}
__device__ __forceinline__ void ldmA(uint32_t a[4], uint32_t addr) {
    asm volatile("ldmatrix.sync.aligned.m8n8.x4.shared.b16 {%0,%1,%2,%3}, [%4];"
                 : "=r"(a[0]), "=r"(a[1]), "=r"(a[2]), "=r"(a[3]) : "r"(addr));
}
__device__ __forceinline__ void ldmB(uint32_t b[2], uint32_t addr) {
    asm volatile("ldmatrix.sync.aligned.m8n8.x2.shared.b16 {%0,%1}, [%2];"
                 : "=r"(b[0]), "=r"(b[1]) : "r"(addr));
}
__device__ __forceinline__ void ldmBT(uint32_t b[2], uint32_t addr) {
    asm volatile("ldmatrix.sync.aligned.m8n8.x2.trans.shared.b16 {%0,%1}, [%2];"
                 : "=r"(b[0]), "=r"(b[1]) : "r"(addr));
}
__device__ __forceinline__ void mma16816(float d[4], const uint32_t a[4],
                                         const uint32_t b[2]) {
    asm volatile(
        "mma.sync.aligned.m16n8k16.row.col.f32.bf16.bf16.f32 "
        "{%0,%1,%2,%3}, {%4,%5,%6,%7}, {%8,%9}, {%0,%1,%2,%3};"
        : "+f"(d[0]), "+f"(d[1]), "+f"(d[2]), "+f"(d[3])
        : "r"(a[0]), "r"(a[1]), "r"(a[2]), "r"(a[3]), "r"(b[0]), "r"(b[1]));
}
__device__ __forceinline__ void cvt_pair(float a, float b, uint32_t& hi, uint32_t& lo) {
    __nv_bfloat162 h = __floats2bfloat162_rn(a, b);
    float2 hf = __bfloat1622float2(h);
    __nv_bfloat162 l = __floats2bfloat162_rn(a - hf.x, b - hf.y);
    hi = *(uint32_t*)&h;
    lo = *(uint32_t*)&l;
}

__global__ void __launch_bounds__(512, 1)
fast_attn_hmma(const float* __restrict__ q, const float* __restrict__ k,
               const float* __restrict__ v, const float* __restrict__ rpe,
               float* __restrict__ out)
{
    extern __shared__ __align__(1024) char smc[];
    const uint32_t sb = smem_u32(smc);
    float* Pring = (float*)(smc + RING);
    float* Dsm = (float*)(smc + DEN);

    const int bh = blockIdx.y;
    const int i0 = blockIdx.x * BI;
    const int t = threadIdx.x, lane = t & 31, w = t >> 5;
    const int wi = w >> 2, wj = w & 3;   // warp: rows wi*32..+31, j-cols wj*16..+15
    const int qr = lane >> 2, qc = (lane & 3) * 2;

    const uint32_t xl   = (uint32_t)(lane & 7) << 4;
    const uint32_t aoff = ((uint32_t)((lane & 7) + (lane & 8)) << 7) |
                          (((uint32_t)(lane >> 4) & 1) << 4);
    const uint32_t boff = ((uint32_t)(lane & 7) << 7) |
                          (((uint32_t)(lane >> 3) & 1) << 4);
    const uint32_t voff = (uint32_t)(lane & 15) << 7;

    const float* qb = q + (size_t)bh * NSEQ * 64;
    const float* kb = k + (size_t)bh * NSEQ * 64;
    const float* vb = v + (size_t)bh * NSEQ * 64;

    // ---- convert Q tile once (128x64 -> bf16 hi/lo) ----
    #pragma unroll
    for (int it = 0; it < 4; ++it) {
        int e = t + it * 512;
        int row = e >> 4, c4 = e & 15;
        float4 x = *(const float4*)(qb + (size_t)(i0 + row) * 64 + c4 * 4);
        uint32_t h0, l0, h1, l1;
        cvt_pair(x.x, x.y, h0, l0);
        cvt_pair(x.z, x.w, h1, l1);
        uint32_t sw = SWZ((uint32_t)(row * 128 + c4 * 8));
        *(uint2*)(smc + Q_HI + sw) = make_uint2(h0, h1);
        *(uint2*)(smc + Q_LO + sw) = make_uint2(l0, l1);
    }
    if (t < 128) Dsm[t] = 0.f;
    __syncthreads();

    // ---- preload Q_HI A-fragments (tile-invariant) ----
    uint32_t qA[2][4][4];
    #pragma unroll
    for (int mt = 0; mt < 2; ++mt)
        #pragma unroll
        for (int kk = 0; kk < 4; ++kk)
            ldmA(qA[mt][kk], sb + Q_HI +
                 ((((uint32_t)(wi*32 + mt*16) << 7) + aoff + kk*32) ^ xl));

    // band MMA + ring stage for the R currently in smem
    auto band_stage = [&](int ustart) {
        float bacc[2][2][4];
        #pragma unroll
        for (int a = 0; a < 2; ++a)
            #pragma unroll
            for (int b = 0; b < 2; ++b)
                #pragma unroll
                for (int r = 0; r < 4; ++r) bacc[a][b][r] = 0.f;
        #pragma unroll
        for (int p = 0; p < 2; ++p) {
            uint32_t Bb = (p == 0) ? R_HI : R_LO;
            #pragma unroll
            for (int kk = 0; kk < 4; ++kk) {
                uint32_t B[2][2];
                #pragma unroll
                for (int nt = 0; nt < 2; ++nt)
                    ldmB(B[nt], sb + Bb +
                         ((((uint32_t)(wj*16 + nt*8) << 7) + boff + kk*32) ^ xl));
                #pragma unroll
                for (int mt = 0; mt < 2; ++mt)
                    #pragma unroll
                    for (int nt = 0; nt < 2; ++nt)
                        mma16816(bacc[mt][nt], qA[mt][kk], B[nt]);
            }
        }
        #pragma unroll
        for (int kk = 0; kk < 4; ++kk) {   // Q_LO x R_HI
            uint32_t A[2][4], B[2][2];
            #pragma unroll
            for (int mt = 0; mt < 2; ++mt)
                ldmA(A[mt], sb + Q_LO +
                     ((((uint32_t)(wi*32 + mt*16) << 7) + aoff + kk*32) ^ xl));
            #pragma unroll
            for (int nt = 0; nt < 2; ++nt)
                ldmB(B[nt], sb + R_HI +
                     ((((uint32_t)(wj*16 + nt*8) << 7) + boff + kk*32) ^ xl));
            #pragma unroll
            for (int mt = 0; mt < 2; ++mt)
                #pragma unroll
                for (int nt = 0; nt < 2; ++nt)
                    mma16816(bacc[mt][nt], A[mt], B[nt]);
        }
        const int base_s = ustart % 192;
        #pragma unroll
        for (int mt = 0; mt < 2; ++mt)
            #pragma unroll
            for (int nt = 0; nt < 2; ++nt) {
                int row = wi*32 + mt*16 + qr;
                int slot = base_s + wj*16 + nt*8 + qc;
                *(float2*)&Pring[row * RSTR + slot] =
                    make_float2(bacc[mt][nt][0], bacc[mt][nt][1]);
                *(float2*)&Pring[(row + 8) * RSTR + slot] =
                    make_float2(bacc[mt][nt][2], bacc[mt][nt][3]);
            }
    };

    float oacc[2][8][4];   // warp-partial O over its 16 j's; n covers all 64 d
    float dsum[4];
    #pragma unroll
    for (int a = 0; a < 2; ++a)
        #pragma unroll
        for (int b = 0; b < 8; ++b)
            #pragma unroll
            for (int r = 0; r < 4; ++r) oacc[a][b][r] = 0.f;
    #pragma unroll
    for (int u = 0; u < 4; ++u) dsum[u] = 0.f;

    for (int tile = 0; tile < NT; ++tile) {
        const int j0 = tile * BJ;
        __syncthreads();   // prev gather/SV smem reads done; tiles writable

        // ---- convert K tile ----
        #pragma unroll
        for (int it = 0; it < 2; ++it) {
            int e = t + it * 512;
            int row = e >> 4, c4 = e & 15;
            float4 x = *(const float4*)(kb + (size_t)(j0 + row) * 64 + c4 * 4);
            uint32_t h0, l0, h1, l1;
            cvt_pair(x.x, x.y, h0, l0);
            cvt_pair(x.z, x.w, h1, l1);
            uint32_t sw = SWZ((uint32_t)(row * 128 + c4 * 8));
            *(uint2*)(smc + K_HI + sw) = make_uint2(h0, h1);
            *(uint2*)(smc + K_LO + sw) = make_uint2(l0, l1);
        }
        // ---- convert V tile (natural [j][d]) ----
        #pragma unroll
        for (int it = 0; it < 2; ++it) {
            int e = t + it * 512;
            int row = e >> 4, c4 = e & 15;
            float4 x = *(const float4*)(vb + (size_t)(j0 + row) * 64 + c4 * 4);
            uint32_t h0, l0, h1, l1;
            cvt_pair(x.x, x.y, h0, l0);
            cvt_pair(x.z, x.w, h1, l1);
            uint32_t sw = SWZ((uint32_t)(row * 128 + c4 * 8));
            *(uint2*)(smc + V_HI + sw) = make_uint2(h0, h1);
            *(uint2*)(smc + V_LO + sw) = make_uint2(l0, l1);
        }

        // ---- band ring: new u-columns (3 groups at tile 0, else 1) ----
        const int ngroups = (tile == 0) ? 3 : 1;
        for (int g = 0; g < ngroups; ++g) {
            const int ustart = i0 + 960 - 64 * tile + 64 * g;
            #pragma unroll
            for (int it = 0; it < 2; ++it) {
                int e = t + it * 512;
                int row = e >> 4, c4 = e & 15;
                int gr = ustart + row; if (gr > 2046) gr = 2046;
                float4 x = *(const float4*)(rpe + (size_t)gr * 64 + c4 * 4);
                uint32_t h0, l0, h1, l1;
                cvt_pair(x.x, x.y, h0, l0);
                cvt_pair(x.z, x.w, h1, l1);
                uint32_t sw = SWZ((uint32_t)(row * 128 + c4 * 8));
                *(uint2*)(smc + R_HI + sw) = make_uint2(h0, h1);
                *(uint2*)(smc + R_LO + sw) = make_uint2(l0, l1);
            }
            __syncthreads();
            band_stage(ustart);
            if (g < ngroups - 1) __syncthreads();   // R reused next group
        }

        // ---- QK MMAs (between ring stage and its sync, fills latency) ----
        float zacc[2][2][4];
        #pragma unroll
        for (int a = 0; a < 2; ++a)
            #pragma unroll
            for (int b = 0; b < 2; ++b)
                #pragma unroll
                for (int r = 0; r < 4; ++r) zacc[a][b][r] = 0.f;
        #pragma unroll
        for (int p = 0; p < 2; ++p) {
            uint32_t Bb = (p == 0) ? K_HI : K_LO;
            #pragma unroll
            for (int kk = 0; kk < 4; ++kk) {
                uint32_t B[2][2];
                #pragma unroll
                for (int nt = 0; nt < 2; ++nt)
                    ldmB(B[nt], sb + Bb +
                         ((((uint32_t)(wj*16 + nt*8) << 7) + boff + kk*32) ^ xl));
                #pragma unroll
                for (int mt = 0; mt < 2; ++mt)
                    #pragma unroll
                    for (int nt = 0; nt < 2; ++nt)
                        mma16816(zacc[mt][nt], qA[mt][kk], B[nt]);
            }
        }
        #pragma unroll
        for (int kk = 0; kk < 4; ++kk) {   // Q_LO x K_HI
            uint32_t A[2][4], B[2][2];
            #pragma unroll
            for (int mt = 0; mt < 2; ++mt)
                ldmA(A[mt], sb + Q_LO +
                     ((((uint32_t)(wi*32 + mt*16) << 7) + aoff + kk*32) ^ xl));
            #pragma unroll
            for (int nt = 0; nt < 2; ++nt)
                ldmB(B[nt], sb + K_HI +
                     ((((uint32_t)(wj*16 + nt*8) << 7) + boff + kk*32) ^ xl));
            #pragma unroll
            for (int mt = 0; mt < 2; ++mt)
                #pragma unroll
                for (int nt = 0; nt < 2; ++nt)
                    mma16816(zacc[mt][nt], A[mt], B[nt]);
        }
        __syncthreads();   // ring staged; K/R ldm reads done

        // ---- gather band from ring; s-transform; pack A-frags in regs ----
        {
            int gb = (i0 - 64 * tile + 1023) % 192;
            #pragma unroll
            for (int mt = 0; mt < 2; ++mt)
                #pragma unroll
                for (int nt = 0; nt < 2; ++nt)
                    #pragma unroll
                    for (int r = 0; r < 4; ++r) {
                        int ii = wi*32 + mt*16 + qr + ((r >> 1) << 3);
                        int jj = wj*16 + nt*8 + qc + (r & 1);
                        int slot = gb + ii - jj;
                        if (slot >= 192) slot -= 192;
                        zacc[mt][nt][r] += Pring[ii * RSTR + slot];
                    }
        }
        uint32_t sHi[2][4], sLo[2][4];
        #pragma unroll
        for (int mt = 0; mt < 2; ++mt) {
            #pragma unroll
            for (int nt = 0; nt < 2; ++nt)
                #pragma unroll
                for (int r = 0; r < 4; ++r) {
                    float z = zacc[mt][nt][r];
                    float s = fmaf(z, fmaf(z, 0.5f, 1.f), 1.f);
                    zacc[mt][nt][r] = s;
                    dsum[mt * 2 + (r >> 1)] += s;
                }
            // C-frag -> A-frag: nt0 gives k=0..7 regs, nt1 gives k=8..15
            cvt_pair(zacc[mt][0][0], zacc[mt][0][1], sHi[mt][0], sLo[mt][0]);
            cvt_pair(zacc[mt][0][2], zacc[mt][0][3], sHi[mt][1], sLo[mt][1]);
            cvt_pair(zacc[mt][1][0], zacc[mt][1][1], sHi[mt][2], sLo[mt][2]);
            cvt_pair(zacc[mt][1][2], zacc[mt][1][3], sHi[mt][3], sLo[mt][3]);
        }

        // ---- SV MMAs: warp k-block = its own j range (wj*16..+15), n = 64 d ----
        #pragma unroll
        for (int nt = 0; nt < 8; ++nt) {      // S_HI x V_HI
            uint32_t B[2];
            ldmBT(B, sb + V_HI +
                  ((((uint32_t)(wj*16) << 7) + voff + (uint32_t)(nt*16)) ^ xl));
            #pragma unroll
            for (int mt = 0; mt < 2; ++mt)
                mma16816(oacc[mt][nt], sHi[mt], B);
        }
        #pragma unroll
        for (int nt = 0; nt < 8; ++nt) {      // S_HI x V_LO
            uint32_t B[2];
            ldmBT(B, sb + V_LO +
                  ((((uint32_t)(wj*16) << 7) + voff + (uint32_t)(nt*16)) ^ xl));
            #pragma unroll
            for (int mt = 0; mt < 2; ++mt)
                mma16816(oacc[mt][nt], sHi[mt], B);
        }
        #pragma unroll
        for (int nt = 0; nt < 8; ++nt) {      // S_LO x V_HI
            uint32_t B[2];
            ldmBT(B, sb + V_HI +
                  ((((uint32_t)(wj*16) << 7) + voff + (uint32_t)(nt*16)) ^ xl));
            #pragma unroll
            for (int mt = 0; mt < 2; ++mt)
                mma16816(oacc[mt][nt], sLo[mt], B);
        }
    }

    // ---- reduce denominators ----
    #pragma unroll
    for (int u = 0; u < 4; ++u) {
        float s = dsum[u];
        s += __shfl_xor_sync(0xffffffffu, s, 1);
        s += __shfl_xor_sync(0xffffffffu, s, 2);
        if ((lane & 3) == 0)
            atomicAdd(&Dsm[wi*32 + (u >> 1)*16 + qr + ((u & 1) << 3)], s);
    }
    __syncthreads();   // Dsm complete; all loop smem reads done

    // ---- staged cross-warp O reduction into f32 buffer (aliases dead Q/K) ----
    float* Obuf = (float*)smc;   // 128 rows x 68 stride
    #pragma unroll
    for (int stage = 0; stage < 4; ++stage) {
        if (wj == stage) {
            #pragma unroll
            for (int mt = 0; mt < 2; ++mt)
                #pragma unroll
                for (int nt = 0; nt < 8; ++nt) {
                    int row = wi*32 + mt*16 + qr;
                    int col = nt*8 + qc;
                    float* p0 = &Obuf[row * 68 + col];
                    float* p1 = &Obuf[(row + 8) * 68 + col];
                    if (stage == 0) {
                        p0[0] = oacc[mt][nt][0]; p0[1] = oacc[mt][nt][1];
                        p1[0] = oacc[mt][nt][2]; p1[1] = oacc[mt][nt][3];
                    } else {
                        p0[0] += oacc[mt][nt][0]; p0[1] += oacc[mt][nt][1];
                        p1[0] += oacc[mt][nt][2]; p1[1] += oacc[mt][nt][3];
                    }
                }
        }
        __syncthreads();
    }

    // ---- final: divide and store ----
    #pragma unroll
    for (int it = 0; it < 4; ++it) {
        int e = t + it * 512;
        int row = e >> 4, c4 = e & 15;
        float inv = 1.0f / Dsm[row];
        const float* p = &Obuf[row * 68 + c4 * 4];
        float4 o = make_float4(p[0] * inv, p[1] * inv, p[2] * inv, p[3] * inv);
        *(float4*)(out + ((size_t)(bh * NSEQ + i0 + row)) * 64 + c4 * 4) = o;
    }
}

extern "C" void kernel_launch(void* const* d_in, const int* in_sizes, int n_in,
                              void* d_out, int out_size)
{
    const float* q   = (const float*)d_in[0];
    const float* k   = (const float*)d_in[1];
    const float* v   = (const float*)d_in[2];
    // d_in[3] = drop_noise (unused)
    const float* rpe = (const float*)d_in[4];
    float* out = (float*)d_out;

    cudaFuncSetAttribute(fast_attn_hmma,
                         cudaFuncAttributeMaxDynamicSharedMemorySize, SMEM_BYTES);
    dim3 grid(NSEQ / BI, 16);   // 8 x 16 = 128 CTAs, one wave
    fast_attn_hmma<<<grid, 512, SMEM_BYTES>>>(q, k, v, rpe, out);
}

// round 10
// speedup vs baseline: 1.3153x; 1.3153x over previous
#include <cuda_runtime.h>
#include <cuda_bf16.h>
#include <cstdint>

// Degree-2 Taylor attention with RPE via warp-level mma.sync (bf16 x3-split)
// + rolling band ring + tail-pipelined converts (3 barriers/tile).
// BI=128, BJ=64, 512 threads (16 warps), grid 8 x 16 = 128 CTAs, 1 CTA/SM.

constexpr int NSEQ = 1024, BI = 128, BJ = 64, NT = NSEQ / BJ;
constexpr int RSTR = 200;   // ring stride in floats

// smem byte offsets
constexpr int Q_HI = 0,      Q_LO = 16384;   // 128x64 bf16
constexpr int K_HI = 32768,  K_LO = 40960;   // 64x64
constexpr int R_HI = 49152,  R_LO = 57344;   // 64 rpe rows
constexpr int V_HI = 65536,  V_LO = 73728;   // 64x64 natural
constexpr int S_HI = 81920,  S_LO = 98304;   // 128x64
constexpr int RING = 114688;                 // 128 x 200 f32 ring
constexpr int DEN  = RING + 128 * RSTR * 4;  // 217088
constexpr int SMEM_BYTES = DEN + 512;        // 217600

#define SWZ(o) ((o) ^ ((((o) >> 7) & 7) << 4))

__device__ __forceinline__ uint32_t smem_u32(const void* p) {
    uint32_t a;
    asm("{ .reg .u64 t; cvta.to.shared.u64 t, %1; cvt.u32.u64 %0, t; }"
        : "=r"(a) : "l"(p));
    return a;
}
__device__ __forceinline__ void ldmA(uint32_t a[4], uint32_t addr) {
    asm volatile("ldmatrix.sync.aligned.m8n8.x4.shared.b16 {%0,%1,%2,%3}, [%4];"
                 : "=r"(a[0]), "=r"(a[1]), "=r"(a[2]), "=r"(a[3]) : "r"(addr));
}
__device__ __forceinline__ void ldmB(uint32_t b[2], uint32_t addr) {
    asm volatile("ldmatrix.sync.aligned.m8n8.x2.shared.b16 {%0,%1}, [%2];"
                 : "=r"(b[0]), "=r"(b[1]) : "r"(addr));
}
__device__ __forceinline__ void ldmBT(uint32_t b[2], uint32_t addr) {
    asm volatile("ldmatrix.sync.aligned.m8n8.x2.trans.shared.b16 {%0,%1}, [%2];"
                 : "=r"(b[0]), "=r"(b[1]) : "r"(addr));
}
__device__ __forceinline__ void mma16816(float d[4], const uint32_t a[4],
                                         const uint32_t b[2]) {
    asm volatile(
        "mma.sync.aligned.m16n8k16.row.col.f32.bf16.bf16.f32 "
        "{%0,%1,%2,%3}, {%4,%5,%6,%7}, {%8,%9}, {%0,%1,%2,%3};"
        : "+f"(d[0]), "+f"(d[1]), "+f"(d[2]), "+f"(d[3])
        : "r"(a[0]), "r"(a[1]), "r"(a[2]), "r"(a[3]), "r"(b[0]), "r"(b[1]));
}
__device__ __forceinline__ void cvt_pair(float a, float b, uint32_t& hi, uint32_t& lo) {
    __nv_bfloat162 h = __floats2bfloat162_rn(a, b);
    float2 hf = __bfloat1622float2(h);
    __nv_bfloat162 l = __floats2bfloat162_rn(a - hf.x, b - hf.y);
    hi = *(uint32_t*)&h;
    lo = *(uint32_t*)&l;
}
// per-thread 8-float slice of a 64x64 tile
__device__ __forceinline__ void ldg8(const float* base, int t, float4& a, float4& b) {
    a = *(const float4*)(base + (size_t)(t >> 4) * 64 + (t & 15) * 4);
    b = *(const float4*)(base + (size_t)((t >> 4) + 32) * 64 + (t & 15) * 4);
}
__device__ __forceinline__ void ldg8_rpe(const float* rpe, int ustart, int t,
                                         float4& a, float4& b) {
    int r0 = ustart + (t >> 4);      if (r0 > 2046) r0 = 2046;
    int r1 = ustart + (t >> 4) + 32; if (r1 > 2046) r1 = 2046;
    a = *(const float4*)(rpe + (size_t)r0 * 64 + (t & 15) * 4);
    b = *(const float4*)(rpe + (size_t)r1 * 64 + (t & 15) * 4);
}
__device__ __forceinline__ void cvt8(float4 a, float4 b, uint32_t h[4], uint32_t l[4]) {
    cvt_pair(a.x, a.y, h[0], l[0]); cvt_pair(a.z, a.w, h[1], l[1]);
    cvt_pair(b.x, b.y, h[2], l[2]); cvt_pair(b.z, b.w, h[3], l[3]);
}
__device__ __forceinline__ void sts8(char* smc, int HI, int LO, int t,
                                     const uint32_t h[4], const uint32_t l[4]) {
    uint32_t sw0 = SWZ((uint32_t)((t >> 4) * 128 + (t & 15) * 8));
    uint32_t sw1 = SWZ((uint32_t)(((t >> 4) + 32) * 128 + (t & 15) * 8));
    *(uint2*)(smc + HI + sw0) = make_uint2(h[0], h[1]);
    *(uint2*)(smc + LO + sw0) = make_uint2(l[0], l[1]);
    *(uint2*)(smc + HI + sw1) = make_uint2(h[2], h[3]);
    *(uint2*)(smc + LO + sw1) = make_uint2(l[2], l[3]);
}

__global__ void __launch_bounds__(512, 1)
fast_attn_hmma(const float* __restrict__ q, const float* __restrict__ k,
               const float* __restrict__ v, const float* __restrict__ rpe,
               float* __restrict__ out)
{
    extern __shared__ __align__(1024) char smc[];
    const uint32_t sb = smem_u32(smc);
    float* Pring = (float*)(smc + RING);
    float* Dsm = (float*)(smc + DEN);

    const int bh = blockIdx.y;
    const int i0 = blockIdx.x * BI;
    const int t = threadIdx.x, lane = t & 31, w = t >> 5;
    const int wi = w >> 2, wj = w & 3;
    const int qr = lane >> 2, qc = (lane & 3) * 2;

    const uint32_t xl   = (uint32_t)(lane & 7) << 4;
    const uint32_t xs   = (uint32_t)qr << 4;
    const uint32_t aoff = ((uint32_t)((lane & 7) + (lane & 8)) << 7) |
                          (((uint32_t)(lane >> 4) & 1) << 4);
    const uint32_t boff = ((uint32_t)(lane & 7) << 7) |
                          (((uint32_t)(lane >> 3) & 1) << 4);
    const uint32_t voff = (uint32_t)(lane & 15) << 7;

    const float* qb = q + (size_t)bh * NSEQ * 64;
    const float* kb = k + (size_t)bh * NSEQ * 64;
    const float* vb = v + (size_t)bh * NSEQ * 64;

    // ---- convert Q tile once (128x64 -> bf16 hi/lo) ----
    #pragma unroll
    for (int it = 0; it < 4; ++it) {
        int e = t + it * 512;
        int row = e >> 4, c4 = e & 15;
        float4 x = *(const float4*)(qb + (size_t)(i0 + row) * 64 + c4 * 4);
        uint32_t h0, l0, h1, l1;
        cvt_pair(x.x, x.y, h0, l0);
        cvt_pair(x.z, x.w, h1, l1);
        uint32_t sw = SWZ((uint32_t)(row * 128 + c4 * 8));
        *(uint2*)(smc + Q_HI + sw) = make_uint2(h0, h1);
        *(uint2*)(smc + Q_LO + sw) = make_uint2(l0, l1);
    }
    if (t < 128) Dsm[t] = 0.f;
    __syncthreads();

    // ---- preload Q_HI A-fragments (tile-invariant) ----
    uint32_t qA[2][4][4];
    #pragma unroll
    for (int mt = 0; mt < 2; ++mt)
        #pragma unroll
        for (int kk = 0; kk < 4; ++kk)
            ldmA(qA[mt][kk], sb + Q_HI +
                 ((((uint32_t)(wi*32 + mt*16) << 7) + aoff + kk*32) ^ xl));

    // band MMA + ring stage for the R currently in smem (window base ustart)
    auto band_stage = [&](int ustart) {
        float bacc[2][2][4];
        #pragma unroll
        for (int a = 0; a < 2; ++a)
            #pragma unroll
            for (int b = 0; b < 2; ++b)
                #pragma unroll
                for (int r = 0; r < 4; ++r) bacc[a][b][r] = 0.f;
        #pragma unroll
        for (int p = 0; p < 2; ++p) {
            uint32_t Bb = (p == 0) ? R_HI : R_LO;
            #pragma unroll
            for (int kk = 0; kk < 4; ++kk) {
                uint32_t B[2][2];
                #pragma unroll
                for (int nt = 0; nt < 2; ++nt)
                    ldmB(B[nt], sb + Bb +
                         ((((uint32_t)(wj*16 + nt*8) << 7) + boff + kk*32) ^ xl));
                #pragma unroll
                for (int mt = 0; mt < 2; ++mt)
                    #pragma unroll
                    for (int nt = 0; nt < 2; ++nt)
                        mma16816(bacc[mt][nt], qA[mt][kk], B[nt]);
            }
        }
        #pragma unroll
        for (int kk = 0; kk < 4; ++kk) {   // Q_LO x R_HI
            uint32_t A[2][4], B[2][2];
            #pragma unroll
            for (int mt = 0; mt < 2; ++mt)
                ldmA(A[mt], sb + Q_LO +
                     ((((uint32_t)(wi*32 + mt*16) << 7) + aoff + kk*32) ^ xl));
            #pragma unroll
            for (int nt = 0; nt < 2; ++nt)
                ldmB(B[nt], sb + R_HI +
                     ((((uint32_t)(wj*16 + nt*8) << 7) + boff + kk*32) ^ xl));
            #pragma unroll
            for (int mt = 0; mt < 2; ++mt)
                #pragma unroll
                for (int nt = 0; nt < 2; ++nt)
                    mma16816(bacc[mt][nt], A[mt], B[nt]);
        }
        const int base_s = ustart % 192;
        #pragma unroll
        for (int mt = 0; mt < 2; ++mt)
            #pragma unroll
            for (int nt = 0; nt < 2; ++nt) {
                int row = wi*32 + mt*16 + qr;
                int slot = base_s + wj*16 + nt*8 + qc;
                *(float2*)&Pring[row * RSTR + slot] =
                    make_float2(bacc[mt][nt][0], bacc[mt][nt][1]);
                *(float2*)&Pring[(row + 8) * RSTR + slot] =
                    make_float2(bacc[mt][nt][2], bacc[mt][nt][3]);
            }
    };

    // ---- preamble: convert K(0), V(0); stage band groups g=1,2; convert R(0) ----
    {
        float4 a, b; uint32_t h[4], l[4];
        ldg8(kb, t, a, b); cvt8(a, b, h, l); sts8(smc, K_HI, K_LO, t, h, l);
        ldg8(vb, t, a, b); cvt8(a, b, h, l); sts8(smc, V_HI, V_LO, t, h, l);
        #pragma unroll
        for (int g = 1; g <= 2; ++g) {
            int ustart = i0 + 960 + 64 * g;
            ldg8_rpe(rpe, ustart, t, a, b);
            cvt8(a, b, h, l); sts8(smc, R_HI, R_LO, t, h, l);
            __syncthreads();
            band_stage(ustart);
            __syncthreads();
        }
        ldg8_rpe(rpe, i0 + 960, t, a, b);
        cvt8(a, b, h, l); sts8(smc, R_HI, R_LO, t, h, l);
        __syncthreads();
    }

    float oacc[2][2][4];
    float dsum[4];
    #pragma unroll
    for (int a = 0; a < 2; ++a)
        #pragma unroll
        for (int b = 0; b < 2; ++b)
            #pragma unroll
            for (int r = 0; r < 4; ++r) oacc[a][b][r] = 0.f;
    #pragma unroll
    for (int u = 0; u < 4; ++u) dsum[u] = 0.f;

    for (int tile = 0; tile < NT; ++tile) {
        const int j0 = tile * BJ;

        // step 1: band MMA + ring stage (reads R(t)); ring STS overlaps QK below
        band_stage(i0 + 960 - 64 * tile);

        // step 2: QK MMAs: zacc = Q K^T (3-split; reads K(t))
        float zacc[2][2][4];
        #pragma unroll
        for (int a = 0; a < 2; ++a)
            #pragma unroll
            for (int b = 0; b < 2; ++b)
                #pragma unroll
                for (int r = 0; r < 4; ++r) zacc[a][b][r] = 0.f;
        #pragma unroll
        for (int p = 0; p < 2; ++p) {
            uint32_t Bb = (p == 0) ? K_HI : K_LO;
            #pragma unroll
            for (int kk = 0; kk < 4; ++kk) {
                uint32_t B[2][2];
                #pragma unroll
                for (int nt = 0; nt < 2; ++nt)
                    ldmB(B[nt], sb + Bb +
                         ((((uint32_t)(wj*16 + nt*8) << 7) + boff + kk*32) ^ xl));
                #pragma unroll
                for (int mt = 0; mt < 2; ++mt)
                    #pragma unroll
                    for (int nt = 0; nt < 2; ++nt)
                        mma16816(zacc[mt][nt], qA[mt][kk], B[nt]);
            }
        }
        #pragma unroll
        for (int kk = 0; kk < 4; ++kk) {   // Q_LO x K_HI
            uint32_t A[2][4], B[2][2];
            #pragma unroll
            for (int mt = 0; mt < 2; ++mt)
                ldmA(A[mt], sb + Q_LO +
                     ((((uint32_t)(wi*32 + mt*16) << 7) + aoff + kk*32) ^ xl));
            #pragma unroll
            for (int nt = 0; nt < 2; ++nt)
                ldmB(B[nt], sb + K_HI +
                     ((((uint32_t)(wj*16 + nt*8) << 7) + boff + kk*32) ^ xl));
            #pragma unroll
            for (int mt = 0; mt < 2; ++mt)
                #pragma unroll
                for (int nt = 0; nt < 2; ++nt)
                    mma16816(zacc[mt][nt], A[mt], B[nt]);
        }
        __syncthreads();   // A: ring staged; K/R reads done; V(t)/K(t)/R(t) visible

        // step 3: gather band from ring; s-transform; S store
        {
            int gb = (i0 - 64 * tile + 1023) % 192;
            #pragma unroll
            for (int mt = 0; mt < 2; ++mt)
                #pragma unroll
                for (int nt = 0; nt < 2; ++nt)
                    #pragma unroll
                    for (int r = 0; r < 4; ++r) {
                        int ii = wi*32 + mt*16 + qr + ((r >> 1) << 3);
                        int jj = wj*16 + nt*8 + qc + (r & 1);
                        int slot = gb + ii - jj;
                        if (slot >= 192) slot -= 192;
                        zacc[mt][nt][r] += Pring[ii * RSTR + slot];
                    }
        }
        #pragma unroll
        for (int mt = 0; mt < 2; ++mt)
            #pragma unroll
            for (int nt = 0; nt < 2; ++nt)
                #pragma unroll
                for (int r = 0; r < 4; ++r) {
                    float z = zacc[mt][nt][r];
                    float s = fmaf(z, fmaf(z, 0.5f, 1.f), 1.f);
                    zacc[mt][nt][r] = s;
                    dsum[mt * 2 + (r >> 1)] += s;
                }
        #pragma unroll
        for (int mt = 0; mt < 2; ++mt)
            #pragma unroll
            for (int nt = 0; nt < 2; ++nt) {
                int r0 = wi*32 + mt*16 + qr;
                int c0 = wj*16 + nt*8 + qc;
                uint32_t h0, l0, h1, l1;
                cvt_pair(zacc[mt][nt][0], zacc[mt][nt][1], h0, l0);
                cvt_pair(zacc[mt][nt][2], zacc[mt][nt][3], h1, l1);
                uint32_t off0 = ((uint32_t)(r0 * 128 + c0 * 2)) ^ xs;
                *(uint32_t*)(smc + S_HI + off0) = h0;
                *(uint32_t*)(smc + S_LO + off0) = l0;
                *(uint32_t*)(smc + S_HI + off0 + 1024) = h1;
                *(uint32_t*)(smc + S_LO + off0 + 1024) = l1;
            }
        __syncthreads();   // B: S visible

        // step 4: prefetch next tile's K/V/rpe (zacc dead; hides under SV MMAs)
        float4 kf0, kf1, rf0, rf1, vf0, vf1;
        if (tile < NT - 1) {
            ldg8(kb + (size_t)(j0 + 64) * 64, t, kf0, kf1);
            ldg8(vb + (size_t)(j0 + 64) * 64, t, vf0, vf1);
            ldg8_rpe(rpe, i0 + 960 - 64 * (tile + 1), t, rf0, rf1);
        }

        // step 5: SV MMAs: O += S V (3-split; no operand caching — min regs)
        #pragma unroll
        for (int kk = 0; kk < 4; ++kk) {
            uint32_t A[2][4], A2[2][4], Bh[2][2], Bl[2][2];
            #pragma unroll
            for (int mt = 0; mt < 2; ++mt)
                ldmA(A[mt], sb + S_HI +
                     ((((uint32_t)(wi*32 + mt*16) << 7) + aoff + kk*32) ^ xl));
            #pragma unroll
            for (int nt = 0; nt < 2; ++nt)
                ldmBT(Bh[nt], sb + V_HI +
                      ((((uint32_t)(kk*16) << 7) + voff +
                        (uint32_t)(wj*32 + nt*16)) ^ xl));
            #pragma unroll
            for (int mt = 0; mt < 2; ++mt)     // S_HI x V_HI
                #pragma unroll
                for (int nt = 0; nt < 2; ++nt)
                    mma16816(oacc[mt][nt], A[mt], Bh[nt]);
            #pragma unroll
            for (int nt = 0; nt < 2; ++nt)
                ldmBT(Bl[nt], sb + V_LO +
                      ((((uint32_t)(kk*16) << 7) + voff +
                        (uint32_t)(wj*32 + nt*16)) ^ xl));
            #pragma unroll
            for (int mt = 0; mt < 2; ++mt)     // S_HI x V_LO
                #pragma unroll
                for (int nt = 0; nt < 2; ++nt)
                    mma16816(oacc[mt][nt], A[mt], Bl[nt]);
            #pragma unroll
            for (int mt = 0; mt < 2; ++mt)
                ldmA(A2[mt], sb + S_LO +
                     ((((uint32_t)(wi*32 + mt*16) << 7) + aoff + kk*32) ^ xl));
            #pragma unroll
            for (int mt = 0; mt < 2; ++mt)     // S_LO x V_HI
                #pragma unroll
                for (int nt = 0; nt < 2; ++nt)
                    mma16816(oacc[mt][nt], A2[mt], Bh[nt]);
        }

        // step 6: convert+store next K/R (their reads ended at sync A)
        if (tile < NT - 1) {
            uint32_t h[4], l[4];
            cvt8(kf0, kf1, h, l); sts8(smc, K_HI, K_LO, t, h, l);
            cvt8(rf0, rf1, h, l); sts8(smc, R_HI, R_LO, t, h, l);
        }
        __syncthreads();   // C: SV done (V writable); K/R(t+1) visible

        // step 7: convert+store next V (V reads ended at sync C)
        if (tile < NT - 1) {
            uint32_t h[4], l[4];
            cvt8(vf0, vf1, h, l); sts8(smc, V_HI, V_LO, t, h, l);
        }
        // V(t+1) visibility for SV(t+1) is ordered by syncs A/B of next iter
    }

    // ---- reduce denominators ----
    #pragma unroll
    for (int u = 0; u < 4; ++u) {
        float s = dsum[u];
        s += __shfl_xor_sync(0xffffffffu, s, 1);
        s += __shfl_xor_sync(0xffffffffu, s, 2);
        if ((lane & 3) == 0)
            atomicAdd(&Dsm[wi*32 + (u >> 1)*16 + qr + ((u & 1) << 3)], s);
    }
    __syncthreads();

    // ---- epilogue ----
    #pragma unroll
    for (int mt = 0; mt < 2; ++mt)
        #pragma unroll
        for (int nt = 0; nt < 2; ++nt) {
            int ii = wi*32 + mt*16 + qr;
            int d0 = wj*16 + nt*8 + qc;
            float inv0 = 1.f / Dsm[ii];
            float inv1 = 1.f / Dsm[ii + 8];
            float* o0 = out + ((size_t)(bh * NSEQ + i0 + ii)) * 64 + d0;
            *(float2*)o0 = make_float2(oacc[mt][nt][0] * inv0, oacc[mt][nt][1] * inv0);
            *(float2*)(o0 + 8 * 64) =
                make_float2(oacc[mt][nt][2] * inv1, oacc[mt][nt][3] * inv1);
        }
}

extern "C" void kernel_launch(void* const* d_in, const int* in_sizes, int n_in,
                              void* d_out, int out_size)
{
    const float* q   = (const float*)d_in[0];
    const float* k   = (const float*)d_in[1];
    const float* v   = (const float*)d_in[2];
    // d_in[3] = drop_noise (unused)
    const float* rpe = (const float*)d_in[4];
    float* out = (float*)d_out;

    cudaFuncSetAttribute(fast_attn_hmma,
                         cudaFuncAttributeMaxDynamicSharedMemorySize, SMEM_BYTES);
    dim3 grid(NSEQ / BI, 16);   // 8 x 16 = 128 CTAs, one wave
    fast_attn_hmma<<<grid, 512, SMEM_BYTES>>>(q, k, v, rpe, out);
}

// round 11
// speedup vs baseline: 1.3890x; 1.0560x over previous
#include <cuda_runtime.h>
#include <cuda_bf16.h>
#include <cstdint>

// Degree-2 Taylor attention with RPE via warp-level mma.sync (bf16 x3-split)
// + rolling band ring + L1-prefetch pipelining (zero register cost).
// BI=128, BJ=64, 512 threads (16 warps), grid 8 x 16 = 128 CTAs, 1 CTA/SM.

constexpr int NSEQ = 1024, BI = 128, BJ = 64, NT = NSEQ / BJ;
constexpr int RSTR = 200;   // ring stride in floats

// smem byte offsets
constexpr int Q_HI = 0,      Q_LO = 16384;   // 128x64 bf16
constexpr int K_HI = 32768,  K_LO = 40960;   // 64x64
constexpr int R_HI = 49152,  R_LO = 57344;   // 64 rpe rows
constexpr int V_HI = 65536,  V_LO = 73728;   // 64x64 natural
constexpr int S_HI = 81920,  S_LO = 98304;   // 128x64
constexpr int RING = 114688;                 // 128 x 200 f32 ring
constexpr int DEN  = RING + 128 * RSTR * 4;  // 217088
constexpr int SMEM_BYTES = DEN + 512;        // 217600

#define SWZ(o) ((o) ^ ((((o) >> 7) & 7) << 4))

__device__ __forceinline__ uint32_t smem_u32(const void* p) {
    uint32_t a;
    asm("{ .reg .u64 t; cvta.to.shared.u64 t, %1; cvt.u32.u64 %0, t; }"
        : "=r"(a) : "l"(p));
    return a;
}
__device__ __forceinline__ void ldmA(uint32_t a[4], uint32_t addr) {
    asm volatile("ldmatrix.sync.aligned.m8n8.x4.shared.b16 {%0,%1,%2,%3}, [%4];"
                 : "=r"(a[0]), "=r"(a[1]), "=r"(a[2]), "=r"(a[3]) : "r"(addr));
}
__device__ __forceinline__ void ldmB(uint32_t b[2], uint32_t addr) {
    asm volatile("ldmatrix.sync.aligned.m8n8.x2.shared.b16 {%0,%1}, [%2];"
                 : "=r"(b[0]), "=r"(b[1]) : "r"(addr));
}
__device__ __forceinline__ void ldmBT(uint32_t b[2], uint32_t addr) {
    asm volatile("ldmatrix.sync.aligned.m8n8.x2.trans.shared.b16 {%0,%1}, [%2];"
                 : "=r"(b[0]), "=r"(b[1]) : "r"(addr));
}
__device__ __forceinline__ void mma16816(float d[4], const uint32_t a[4],
                                         const uint32_t b[2]) {
    asm volatile(
        "mma.sync.aligned.m16n8k16.row.col.f32.bf16.bf16.f32 "
        "{%0,%1,%2,%3}, {%4,%5,%6,%7}, {%8,%9}, {%0,%1,%2,%3};"
        : "+f"(d[0]), "+f"(d[1]), "+f"(d[2]), "+f"(d[3])
        : "r"(a[0]), "r"(a[1]), "r"(a[2]), "r"(a[3]), "r"(b[0]), "r"(b[1]));
}
__device__ __forceinline__ void cvt_pair(float a, float b, uint32_t& hi, uint32_t& lo) {
    __nv_bfloat162 h = __floats2bfloat162_rn(a, b);
    float2 hf = __bfloat1622float2(h);
    __nv_bfloat162 l = __floats2bfloat162_rn(a - hf.x, b - hf.y);
    hi = *(uint32_t*)&h;
    lo = *(uint32_t*)&l;
}
__device__ __forceinline__ void pf_l1(const float* p) {
    asm volatile("prefetch.global.L1 [%0];" :: "l"(p));
}

__global__ void __launch_bounds__(512, 1)
fast_attn_hmma(const float* __restrict__ q, const float* __restrict__ k,
               const float* __restrict__ v, const float* __restrict__ rpe,
               float* __restrict__ out)
{
    extern __shared__ __align__(1024) char smc[];
    const uint32_t sb = smem_u32(smc);
    float* Pring = (float*)(smc + RING);
    float* Dsm = (float*)(smc + DEN);

    const int bh = blockIdx.y;
    const int i0 = blockIdx.x * BI;
    const int t = threadIdx.x, lane = t & 31, w = t >> 5;
    const int wi = w >> 2, wj = w & 3;   // warp: rows wi*32..+31, j-cols wj*16..+15
    const int qr = lane >> 2, qc = (lane & 3) * 2;

    const uint32_t xl   = (uint32_t)(lane & 7) << 4;
    const uint32_t xs   = (uint32_t)qr << 4;
    const uint32_t aoff = ((uint32_t)((lane & 7) + (lane & 8)) << 7) |
                          (((uint32_t)(lane >> 4) & 1) << 4);
    const uint32_t boff = ((uint32_t)(lane & 7) << 7) |
                          (((uint32_t)(lane >> 3) & 1) << 4);
    const uint32_t voff = (uint32_t)(lane & 15) << 7;

    const float* qb = q + (size_t)bh * NSEQ * 64;
    const float* kb = k + (size_t)bh * NSEQ * 64;
    const float* vb = v + (size_t)bh * NSEQ * 64;

    // ---- convert Q tile once (128x64 -> bf16 hi/lo) ----
    #pragma unroll
    for (int it = 0; it < 4; ++it) {
        int e = t + it * 512;
        int row = e >> 4, c4 = e & 15;
        float4 x = *(const float4*)(qb + (size_t)(i0 + row) * 64 + c4 * 4);
        uint32_t h0, l0, h1, l1;
        cvt_pair(x.x, x.y, h0, l0);
        cvt_pair(x.z, x.w, h1, l1);
        uint32_t sw = SWZ((uint32_t)(row * 128 + c4 * 8));
        *(uint2*)(smc + Q_HI + sw) = make_uint2(h0, h1);
        *(uint2*)(smc + Q_LO + sw) = make_uint2(l0, l1);
    }
    if (t < 128) Dsm[t] = 0.f;
    __syncthreads();

    // ---- preload Q_HI A-fragments (tile-invariant) ----
    uint32_t qA[2][4][4];
    #pragma unroll
    for (int mt = 0; mt < 2; ++mt)
        #pragma unroll
        for (int kk = 0; kk < 4; ++kk)
            ldmA(qA[mt][kk], sb + Q_HI +
                 ((((uint32_t)(wi*32 + mt*16) << 7) + aoff + kk*32) ^ xl));

    // band MMA + ring stage for the R currently in smem (window base ustart)
    auto band_stage = [&](int ustart) {
        float bacc[2][2][4];
        #pragma unroll
        for (int a = 0; a < 2; ++a)
            #pragma unroll
            for (int b = 0; b < 2; ++b)
                #pragma unroll
                for (int r = 0; r < 4; ++r) bacc[a][b][r] = 0.f;
        #pragma unroll
        for (int p = 0; p < 2; ++p) {
            uint32_t Bb = (p == 0) ? R_HI : R_LO;
            #pragma unroll
            for (int kk = 0; kk < 4; ++kk) {
                uint32_t B[2][2];
                #pragma unroll
                for (int nt = 0; nt < 2; ++nt)
                    ldmB(B[nt], sb + Bb +
                         ((((uint32_t)(wj*16 + nt*8) << 7) + boff + kk*32) ^ xl));
                #pragma unroll
                for (int mt = 0; mt < 2; ++mt)
                    #pragma unroll
                    for (int nt = 0; nt < 2; ++nt)
                        mma16816(bacc[mt][nt], qA[mt][kk], B[nt]);
            }
        }
        #pragma unroll
        for (int kk = 0; kk < 4; ++kk) {   // Q_LO x R_HI
            uint32_t A[2][4], B[2][2];
            #pragma unroll
            for (int mt = 0; mt < 2; ++mt)
                ldmA(A[mt], sb + Q_LO +
                     ((((uint32_t)(wi*32 + mt*16) << 7) + aoff + kk*32) ^ xl));
            #pragma unroll
            for (int nt = 0; nt < 2; ++nt)
                ldmB(B[nt], sb + R_HI +
                     ((((uint32_t)(wj*16 + nt*8) << 7) + boff + kk*32) ^ xl));
            #pragma unroll
            for (int mt = 0; mt < 2; ++mt)
                #pragma unroll
                for (int nt = 0; nt < 2; ++nt)
                    mma16816(bacc[mt][nt], A[mt], B[nt]);
        }
        const int base_s = ustart % 192;
        #pragma unroll
        for (int mt = 0; mt < 2; ++mt)
            #pragma unroll
            for (int nt = 0; nt < 2; ++nt) {
                int row = wi*32 + mt*16 + qr;
                int slot = base_s + wj*16 + nt*8 + qc;
                *(float2*)&Pring[row * RSTR + slot] =
                    make_float2(bacc[mt][nt][0], bacc[mt][nt][1]);
                *(float2*)&Pring[(row + 8) * RSTR + slot] =
                    make_float2(bacc[mt][nt][2], bacc[mt][nt][3]);
            }
    };

    float oacc[2][2][4];
    float dsum[4];
    #pragma unroll
    for (int a = 0; a < 2; ++a)
        #pragma unroll
        for (int b = 0; b < 2; ++b)
            #pragma unroll
            for (int r = 0; r < 4; ++r) oacc[a][b][r] = 0.f;
    #pragma unroll
    for (int u = 0; u < 4; ++u) dsum[u] = 0.f;

    for (int tile = 0; tile < NT; ++tile) {
        const int j0 = tile * BJ;
        __syncthreads();   // prev SV done with S/V; K/V/R writable

        // ---- convert K tile ----
        #pragma unroll
        for (int it = 0; it < 2; ++it) {
            int e = t + it * 512;
            int row = e >> 4, c4 = e & 15;
            float4 x = *(const float4*)(kb + (size_t)(j0 + row) * 64 + c4 * 4);
            uint32_t h0, l0, h1, l1;
            cvt_pair(x.x, x.y, h0, l0);
            cvt_pair(x.z, x.w, h1, l1);
            uint32_t sw = SWZ((uint32_t)(row * 128 + c4 * 8));
            *(uint2*)(smc + K_HI + sw) = make_uint2(h0, h1);
            *(uint2*)(smc + K_LO + sw) = make_uint2(l0, l1);
        }
        // ---- convert V tile (natural [j][d]) ----
        #pragma unroll
        for (int it = 0; it < 2; ++it) {
            int e = t + it * 512;
            int row = e >> 4, c4 = e & 15;
            float4 x = *(const float4*)(vb + (size_t)(j0 + row) * 64 + c4 * 4);
            uint32_t h0, l0, h1, l1;
            cvt_pair(x.x, x.y, h0, l0);
            cvt_pair(x.z, x.w, h1, l1);
            uint32_t sw = SWZ((uint32_t)(row * 128 + c4 * 8));
            *(uint2*)(smc + V_HI + sw) = make_uint2(h0, h1);
            *(uint2*)(smc + V_LO + sw) = make_uint2(l0, l1);
        }

        // ---- band ring: new u-columns (3 groups at tile 0, else 1) ----
        const int ngroups = (tile == 0) ? 3 : 1;
        for (int g = 0; g < ngroups; ++g) {
            const int ustart = i0 + 960 - 64 * tile + 64 * g;
            #pragma unroll
            for (int it = 0; it < 2; ++it) {
                int e = t + it * 512;
                int row = e >> 4, c4 = e & 15;
                int gr = ustart + row; if (gr > 2046) gr = 2046;
                float4 x = *(const float4*)(rpe + (size_t)gr * 64 + c4 * 4);
                uint32_t h0, l0, h1, l1;
                cvt_pair(x.x, x.y, h0, l0);
                cvt_pair(x.z, x.w, h1, l1);
                uint32_t sw = SWZ((uint32_t)(row * 128 + c4 * 8));
                *(uint2*)(smc + R_HI + sw) = make_uint2(h0, h1);
                *(uint2*)(smc + R_LO + sw) = make_uint2(l0, l1);
            }
            __syncthreads();
            band_stage(ustart);
            if (g < ngroups - 1) __syncthreads();   // R reused by next group
        }

        // ---- QK MMAs (overlap ring-STS drain): zacc = Q K^T (3-split) ----
        float zacc[2][2][4];
        #pragma unroll
        for (int a = 0; a < 2; ++a)
            #pragma unroll
            for (int b = 0; b < 2; ++b)
                #pragma unroll
                for (int r = 0; r < 4; ++r) zacc[a][b][r] = 0.f;
        #pragma unroll
        for (int p = 0; p < 2; ++p) {
            uint32_t Bb = (p == 0) ? K_HI : K_LO;
            #pragma unroll
            for (int kk = 0; kk < 4; ++kk) {
                uint32_t B[2][2];
                #pragma unroll
                for (int nt = 0; nt < 2; ++nt)
                    ldmB(B[nt], sb + Bb +
                         ((((uint32_t)(wj*16 + nt*8) << 7) + boff + kk*32) ^ xl));
                #pragma unroll
                for (int mt = 0; mt < 2; ++mt)
                    #pragma unroll
                    for (int nt = 0; nt < 2; ++nt)
                        mma16816(zacc[mt][nt], qA[mt][kk], B[nt]);
            }
        }
        #pragma unroll
        for (int kk = 0; kk < 4; ++kk) {   // Q_LO x K_HI
            uint32_t A[2][4], B[2][2];
            #pragma unroll
            for (int mt = 0; mt < 2; ++mt)
                ldmA(A[mt], sb + Q_LO +
                     ((((uint32_t)(wi*32 + mt*16) << 7) + aoff + kk*32) ^ xl));
            #pragma unroll
            for (int nt = 0; nt < 2; ++nt)
                ldmB(B[nt], sb + K_HI +
                     ((((uint32_t)(wj*16 + nt*8) << 7) + boff + kk*32) ^ xl));
            #pragma unroll
            for (int mt = 0; mt < 2; ++mt)
                #pragma unroll
                for (int nt = 0; nt < 2; ++nt)
                    mma16816(zacc[mt][nt], A[mt], B[nt]);
        }
        __syncthreads();   // A: ring staged; K/R ldm reads done

        // ---- gather band from ring; s-transform; S store ----
        {
            int gb = (i0 - 64 * tile + 1023) % 192;
            #pragma unroll
            for (int mt = 0; mt < 2; ++mt)
                #pragma unroll
                for (int nt = 0; nt < 2; ++nt)
                    #pragma unroll
                    for (int r = 0; r < 4; ++r) {
                        int ii = wi*32 + mt*16 + qr + ((r >> 1) << 3);
                        int jj = wj*16 + nt*8 + qc + (r & 1);
                        int slot = gb + ii - jj;
                        if (slot >= 192) slot -= 192;
                        zacc[mt][nt][r] += Pring[ii * RSTR + slot];
                    }
        }
        #pragma unroll
        for (int mt = 0; mt < 2; ++mt)
            #pragma unroll
            for (int nt = 0; nt < 2; ++nt)
                #pragma unroll
                for (int r = 0; r < 4; ++r) {
                    float z = zacc[mt][nt][r];
                    float s = fmaf(z, fmaf(z, 0.5f, 1.f), 1.f);
                    zacc[mt][nt][r] = s;
                    dsum[mt * 2 + (r >> 1)] += s;
                }
        #pragma unroll
        for (int mt = 0; mt < 2; ++mt)
            #pragma unroll
            for (int nt = 0; nt < 2; ++nt) {
                int r0 = wi*32 + mt*16 + qr;
                int c0 = wj*16 + nt*8 + qc;
                uint32_t h0, l0, h1, l1;
                cvt_pair(zacc[mt][nt][0], zacc[mt][nt][1], h0, l0);
                cvt_pair(zacc[mt][nt][2], zacc[mt][nt][3], h1, l1);
                uint32_t off0 = ((uint32_t)(r0 * 128 + c0 * 2)) ^ xs;
                *(uint32_t*)(smc + S_HI + off0) = h0;
                *(uint32_t*)(smc + S_LO + off0) = l0;
                *(uint32_t*)(smc + S_HI + off0 + 1024) = h1;
                *(uint32_t*)(smc + S_LO + off0 + 1024) = l1;
            }
        __syncthreads();   // B: S visible

        // ---- L1 prefetch hints for tile t+1 (zero register cost) ----
        if (tile < NT - 1 && (t & 7) == 0) {
            int row = t >> 4;                 // 0..31 (only t%16==0 or 8 here)
            const float* kp = kb + (size_t)(j0 + 64) * 64;
            const float* vp = vb + (size_t)(j0 + 64) * 64;
            int un = i0 + 960 - 64 * (tile + 1);
            pf_l1(kp + (size_t)row * 64 + (t & 15) * 4);
            pf_l1(kp + (size_t)(row + 32) * 64 + (t & 15) * 4);
            pf_l1(vp + (size_t)row * 64 + (t & 15) * 4);
            pf_l1(vp + (size_t)(row + 32) * 64 + (t & 15) * 4);
            int g0 = un + row;      if (g0 > 2046) g0 = 2046;
            int g1 = un + row + 32; if (g1 > 2046) g1 = 2046;
            pf_l1(rpe + (size_t)g0 * 64 + (t & 15) * 4);
            pf_l1(rpe + (size_t)g1 * 64 + (t & 15) * 4);
        }

        // ---- SV MMAs: O += S V (3-split; vB cached as in R7) ----
        {
            uint32_t vB[4][2][2];
            #pragma unroll
            for (int kk = 0; kk < 4; ++kk)
                #pragma unroll
                for (int nt = 0; nt < 2; ++nt)
                    ldmBT(vB[kk][nt], sb + V_HI +
                          ((((uint32_t)(kk*16) << 7) + voff +
                            (uint32_t)(wj*32 + nt*16)) ^ xl));
            #pragma unroll
            for (int kk = 0; kk < 4; ++kk) {
                uint32_t A[2][4];
                #pragma unroll
                for (int mt = 0; mt < 2; ++mt)
                    ldmA(A[mt], sb + S_HI +
                         ((((uint32_t)(wi*32 + mt*16) << 7) + aoff + kk*32) ^ xl));
                #pragma unroll
                for (int mt = 0; mt < 2; ++mt)     // S_HI x V_HI
                    #pragma unroll
                    for (int nt = 0; nt < 2; ++nt)
                        mma16816(oacc[mt][nt], A[mt], vB[kk][nt]);
                uint32_t B[2][2];
                #pragma unroll
                for (int nt = 0; nt < 2; ++nt)
                    ldmBT(B[nt], sb + V_LO +
                          ((((uint32_t)(kk*16) << 7) + voff +
                            (uint32_t)(wj*32 + nt*16)) ^ xl));
                #pragma unroll
                for (int mt = 0; mt < 2; ++mt)     // S_HI x V_LO
                    #pragma unroll
                    for (int nt = 0; nt < 2; ++nt)
                        mma16816(oacc[mt][nt], A[mt], B[nt]);
                uint32_t A2[2][4];
                #pragma unroll
                for (int mt = 0; mt < 2; ++mt)
                    ldmA(A2[mt], sb + S_LO +
                         ((((uint32_t)(wi*32 + mt*16) << 7) + aoff + kk*32) ^ xl));
                #pragma unroll
                for (int mt = 0; mt < 2; ++mt)     // S_LO x V_HI
                    #pragma unroll
                    for (int nt = 0; nt < 2; ++nt)
                        mma16816(oacc[mt][nt], A2[mt], vB[kk][nt]);
            }
        }
    }

    // ---- reduce denominators ----
    #pragma unroll
    for (int u = 0; u < 4; ++u) {
        float s = dsum[u];
        s += __shfl_xor_sync(0xffffffffu, s, 1);
        s += __shfl_xor_sync(0xffffffffu, s, 2);
        if ((lane & 3) == 0)
            atomicAdd(&Dsm[wi*32 + (u >> 1)*16 + qr + ((u & 1) << 3)], s);
    }
    __syncthreads();

    // ---- epilogue ----
    #pragma unroll
    for (int mt = 0; mt < 2; ++mt)
        #pragma unroll
        for (int nt = 0; nt < 2; ++nt) {
            int ii = wi*32 + mt*16 + qr;
            int d0 = wj*16 + nt*8 + qc;
            float inv0 = 1.f / Dsm[ii];
            float inv1 = 1.f / Dsm[ii + 8];
            float* o0 = out + ((size_t)(bh * NSEQ + i0 + ii)) * 64 + d0;
            *(float2*)o0 = make_float2(oacc[mt][nt][0] * inv0, oacc[mt][nt][1] * inv0);
            *(float2*)(o0 + 8 * 64) =
                make_float2(oacc[mt][nt][2] * inv1, oacc[mt][nt][3] * inv1);
        }
}

extern "C" void kernel_launch(void* const* d_in, const int* in_sizes, int n_in,
                              void* d_out, int out_size)
{
    const float* q   = (const float*)d_in[0];
    const float* k   = (const float*)d_in[1];
    const float* v   = (const float*)d_in[2];
    // d_in[3] = drop_noise (unused)
    const float* rpe = (const float*)d_in[4];
    float* out = (float*)d_out;

    cudaFuncSetAttribute(fast_attn_hmma,
                         cudaFuncAttributeMaxDynamicSharedMemorySize, SMEM_BYTES);
    dim3 grid(NSEQ / BI, 16);   // 8 x 16 = 128 CTAs, one wave
    fast_attn_hmma<<<grid, 512, SMEM_BYTES>>>(q, k, v, rpe, out);
}

// round 12
// speedup vs baseline: 1.4560x; 1.0482x over previous
#include <cuda_runtime.h>
#include <cuda_bf16.h>
#include <cstdint>

// Degree-2 Taylor attention with RPE via warp-level mma.sync (bf16 x3-split)
// + rolling band ring + L1-prefetch + per-wi-group named barriers.
// BI=128, BJ=64, 512 threads (16 warps), grid 8 x 16 = 128 CTAs, 1 CTA/SM.

constexpr int NSEQ = 1024, BI = 128, BJ = 64, NT = NSEQ / BJ;
constexpr int RSTR = 200;   // ring stride in floats

// smem byte offsets
constexpr int Q_HI = 0,      Q_LO = 16384;   // 128x64 bf16
constexpr int K_HI = 32768,  K_LO = 40960;   // 64x64
constexpr int R_HI = 49152,  R_LO = 57344;   // 64 rpe rows
constexpr int V_HI = 65536,  V_LO = 73728;   // 64x64 natural
constexpr int S_HI = 81920,  S_LO = 98304;   // 128x64
constexpr int RING = 114688;                 // 128 x 200 f32 ring
constexpr int DEN  = RING + 128 * RSTR * 4;  // 217088
constexpr int SMEM_BYTES = DEN + 512;        // 217600

#define SWZ(o) ((o) ^ ((((o) >> 7) & 7) << 4))

__device__ __forceinline__ uint32_t smem_u32(const void* p) {
    uint32_t a;
    asm("{ .reg .u64 t; cvta.to.shared.u64 t, %1; cvt.u32.u64 %0, t; }"
        : "=r"(a) : "l"(p));
    return a;
}
__device__ __forceinline__ void named_bar(int id) {
    asm volatile("bar.sync %0, 128;" :: "r"(id) : "memory");
}
__device__ __forceinline__ void ldmA(uint32_t a[4], uint32_t addr) {
    asm volatile("ldmatrix.sync.aligned.m8n8.x4.shared.b16 {%0,%1,%2,%3}, [%4];"
                 : "=r"(a[0]), "=r"(a[1]), "=r"(a[2]), "=r"(a[3]) : "r"(addr));
}
__device__ __forceinline__ void ldmB(uint32_t b[2], uint32_t addr) {
    asm volatile("ldmatrix.sync.aligned.m8n8.x2.shared.b16 {%0,%1}, [%2];"
                 : "=r"(b[0]), "=r"(b[1]) : "r"(addr));
}
__device__ __forceinline__ void ldmBT(uint32_t b[2], uint32_t addr) {
    asm volatile("ldmatrix.sync.aligned.m8n8.x2.trans.shared.b16 {%0,%1}, [%2];"
                 : "=r"(b[0]), "=r"(b[1]) : "r"(addr));
}
__device__ __forceinline__ void mma16816(float d[4], const uint32_t a[4],
                                         const uint32_t b[2]) {
    asm volatile(
        "mma.sync.aligned.m16n8k16.row.col.f32.bf16.bf16.f32 "
        "{%0,%1,%2,%3}, {%4,%5,%6,%7}, {%8,%9}, {%0,%1,%2,%3};"
        : "+f"(d[0]), "+f"(d[1]), "+f"(d[2]), "+f"(d[3])
        : "r"(a[0]), "r"(a[1]), "r"(a[2]), "r"(a[3]), "r"(b[0]), "r"(b[1]));
}
__device__ __forceinline__ void cvt_pair(float a, float b, uint32_t& hi, uint32_t& lo) {
    __nv_bfloat162 h = __floats2bfloat162_rn(a, b);
    float2 hf = __bfloat1622float2(h);
    __nv_bfloat162 l = __floats2bfloat162_rn(a - hf.x, b - hf.y);
    hi = *(uint32_t*)&h;
    lo = *(uint32_t*)&l;
}
__device__ __forceinline__ void pf_l1(const float* p) {
    asm volatile("prefetch.global.L1 [%0];" :: "l"(p));
}

__global__ void __launch_bounds__(512, 1)
fast_attn_hmma(const float* __restrict__ q, const float* __restrict__ k,
               const float* __restrict__ v, const float* __restrict__ rpe,
               float* __restrict__ out)
{
    extern __shared__ __align__(1024) char smc[];
    const uint32_t sb = smem_u32(smc);
    float* Pring = (float*)(smc + RING);
    float* Dsm = (float*)(smc + DEN);

    const int bh = blockIdx.y;
    const int i0 = blockIdx.x * BI;
    const int t = threadIdx.x, lane = t & 31, w = t >> 5;
    const int wi = w >> 2, wj = w & 3;   // warp: rows wi*32..+31, j-cols wj*16..+15
    const int qr = lane >> 2, qc = (lane & 3) * 2;

    const uint32_t xl   = (uint32_t)(lane & 7) << 4;
    const uint32_t xs   = (uint32_t)qr << 4;
    const uint32_t aoff = ((uint32_t)((lane & 7) + (lane & 8)) << 7) |
                          (((uint32_t)(lane >> 4) & 1) << 4);
    const uint32_t boff = ((uint32_t)(lane & 7) << 7) |
                          (((uint32_t)(lane >> 3) & 1) << 4);
    const uint32_t voff = (uint32_t)(lane & 15) << 7;

    const float* qb = q + (size_t)bh * NSEQ * 64;
    const float* kb = k + (size_t)bh * NSEQ * 64;
    const float* vb = v + (size_t)bh * NSEQ * 64;

    // ---- convert Q tile once (128x64 -> bf16 hi/lo) ----
    #pragma unroll
    for (int it = 0; it < 4; ++it) {
        int e = t + it * 512;
        int row = e >> 4, c4 = e & 15;
        float4 x = *(const float4*)(qb + (size_t)(i0 + row) * 64 + c4 * 4);
        uint32_t h0, l0, h1, l1;
        cvt_pair(x.x, x.y, h0, l0);
        cvt_pair(x.z, x.w, h1, l1);
        uint32_t sw = SWZ((uint32_t)(row * 128 + c4 * 8));
        *(uint2*)(smc + Q_HI + sw) = make_uint2(h0, h1);
        *(uint2*)(smc + Q_LO + sw) = make_uint2(l0, l1);
    }
    if (t < 128) Dsm[t] = 0.f;
    __syncthreads();

    // ---- preload Q_HI A-fragments (tile-invariant) ----
    uint32_t qA[2][4][4];
    #pragma unroll
    for (int mt = 0; mt < 2; ++mt)
        #pragma unroll
        for (int kk = 0; kk < 4; ++kk)
            ldmA(qA[mt][kk], sb + Q_HI +
                 ((((uint32_t)(wi*32 + mt*16) << 7) + aoff + kk*32) ^ xl));

    // band MMA + ring stage for the R currently in smem (window base ustart)
    auto band_stage = [&](int ustart) {
        float bacc[2][2][4];
        #pragma unroll
        for (int a = 0; a < 2; ++a)
            #pragma unroll
            for (int b = 0; b < 2; ++b)
                #pragma unroll
                for (int r = 0; r < 4; ++r) bacc[a][b][r] = 0.f;
        #pragma unroll
        for (int p = 0; p < 2; ++p) {
            uint32_t Bb = (p == 0) ? R_HI : R_LO;
            #pragma unroll
            for (int kk = 0; kk < 4; ++kk) {
                uint32_t B[2][2];
                #pragma unroll
                for (int nt = 0; nt < 2; ++nt)
                    ldmB(B[nt], sb + Bb +
                         ((((uint32_t)(wj*16 + nt*8) << 7) + boff + kk*32) ^ xl));
                #pragma unroll
                for (int mt = 0; mt < 2; ++mt)
                    #pragma unroll
                    for (int nt = 0; nt < 2; ++nt)
                        mma16816(bacc[mt][nt], qA[mt][kk], B[nt]);
            }
        }
        #pragma unroll
        for (int kk = 0; kk < 4; ++kk) {   // Q_LO x R_HI
            uint32_t A[2][4], B[2][2];
            #pragma unroll
            for (int mt = 0; mt < 2; ++mt)
                ldmA(A[mt], sb + Q_LO +
                     ((((uint32_t)(wi*32 + mt*16) << 7) + aoff + kk*32) ^ xl));
            #pragma unroll
            for (int nt = 0; nt < 2; ++nt)
                ldmB(B[nt], sb + R_HI +
                     ((((uint32_t)(wj*16 + nt*8) << 7) + boff + kk*32) ^ xl));
            #pragma unroll
            for (int mt = 0; mt < 2; ++mt)
                #pragma unroll
                for (int nt = 0; nt < 2; ++nt)
                    mma16816(bacc[mt][nt], A[mt], B[nt]);
        }
        const int base_s = ustart % 192;
        #pragma unroll
        for (int mt = 0; mt < 2; ++mt)
            #pragma unroll
            for (int nt = 0; nt < 2; ++nt) {
                int row = wi*32 + mt*16 + qr;
                int slot = base_s + wj*16 + nt*8 + qc;
                *(float2*)&Pring[row * RSTR + slot] =
                    make_float2(bacc[mt][nt][0], bacc[mt][nt][1]);
                *(float2*)&Pring[(row + 8) * RSTR + slot] =
                    make_float2(bacc[mt][nt][2], bacc[mt][nt][3]);
            }
    };

    float oacc[2][2][4];
    float dsum[4];
    #pragma unroll
    for (int a = 0; a < 2; ++a)
        #pragma unroll
        for (int b = 0; b < 2; ++b)
            #pragma unroll
            for (int r = 0; r < 4; ++r) oacc[a][b][r] = 0.f;
    #pragma unroll
    for (int u = 0; u < 4; ++u) dsum[u] = 0.f;

    for (int tile = 0; tile < NT; ++tile) {
        const int j0 = tile * BJ;
        __syncthreads();   // full: prev SV done with S/V; K/V/R writable

        // ---- convert K tile ----
        #pragma unroll
        for (int it = 0; it < 2; ++it) {
            int e = t + it * 512;
            int row = e >> 4, c4 = e & 15;
            float4 x = *(const float4*)(kb + (size_t)(j0 + row) * 64 + c4 * 4);
            uint32_t h0, l0, h1, l1;
            cvt_pair(x.x, x.y, h0, l0);
            cvt_pair(x.z, x.w, h1, l1);
            uint32_t sw = SWZ((uint32_t)(row * 128 + c4 * 8));
            *(uint2*)(smc + K_HI + sw) = make_uint2(h0, h1);
            *(uint2*)(smc + K_LO + sw) = make_uint2(l0, l1);
        }
        // ---- convert V tile (natural [j][d]) ----
        #pragma unroll
        for (int it = 0; it < 2; ++it) {
            int e = t + it * 512;
            int row = e >> 4, c4 = e & 15;
            float4 x = *(const float4*)(vb + (size_t)(j0 + row) * 64 + c4 * 4);
            uint32_t h0, l0, h1, l1;
            cvt_pair(x.x, x.y, h0, l0);
            cvt_pair(x.z, x.w, h1, l1);
            uint32_t sw = SWZ((uint32_t)(row * 128 + c4 * 8));
            *(uint2*)(smc + V_HI + sw) = make_uint2(h0, h1);
            *(uint2*)(smc + V_LO + sw) = make_uint2(l0, l1);
        }

        // ---- band ring: new u-columns (3 groups at tile 0, else 1) ----
        const int ngroups = (tile == 0) ? 3 : 1;
        for (int g = 0; g < ngroups; ++g) {
            const int ustart = i0 + 960 - 64 * tile + 64 * g;
            #pragma unroll
            for (int it = 0; it < 2; ++it) {
                int e = t + it * 512;
                int row = e >> 4, c4 = e & 15;
                int gr = ustart + row; if (gr > 2046) gr = 2046;
                float4 x = *(const float4*)(rpe + (size_t)gr * 64 + c4 * 4);
                uint32_t h0, l0, h1, l1;
                cvt_pair(x.x, x.y, h0, l0);
                cvt_pair(x.z, x.w, h1, l1);
                uint32_t sw = SWZ((uint32_t)(row * 128 + c4 * 8));
                *(uint2*)(smc + R_HI + sw) = make_uint2(h0, h1);
                *(uint2*)(smc + R_LO + sw) = make_uint2(l0, l1);
            }
            __syncthreads();   // full: R (and K/V on g=0) visible to all warps
            band_stage(ustart);
            if (g < ngroups - 1) __syncthreads();   // R reused by next group
        }

        // ---- QK MMAs (overlap ring-STS drain): zacc = Q K^T (3-split) ----
        float zacc[2][2][4];
        #pragma unroll
        for (int a = 0; a < 2; ++a)
            #pragma unroll
            for (int b = 0; b < 2; ++b)
                #pragma unroll
                for (int r = 0; r < 4; ++r) zacc[a][b][r] = 0.f;
        #pragma unroll
        for (int p = 0; p < 2; ++p) {
            uint32_t Bb = (p == 0) ? K_HI : K_LO;
            #pragma unroll
            for (int kk = 0; kk < 4; ++kk) {
                uint32_t B[2][2];
                #pragma unroll
                for (int nt = 0; nt < 2; ++nt)
                    ldmB(B[nt], sb + Bb +
                         ((((uint32_t)(wj*16 + nt*8) << 7) + boff + kk*32) ^ xl));
                #pragma unroll
                for (int mt = 0; mt < 2; ++mt)
                    #pragma unroll
                    for (int nt = 0; nt < 2; ++nt)
                        mma16816(zacc[mt][nt], qA[mt][kk], B[nt]);
            }
        }
        #pragma unroll
        for (int kk = 0; kk < 4; ++kk) {   // Q_LO x K_HI
            uint32_t A[2][4], B[2][2];
            #pragma unroll
            for (int mt = 0; mt < 2; ++mt)
                ldmA(A[mt], sb + Q_LO +
                     ((((uint32_t)(wi*32 + mt*16) << 7) + aoff + kk*32) ^ xl));
            #pragma unroll
            for (int nt = 0; nt < 2; ++nt)
                ldmB(B[nt], sb + K_HI +
                     ((((uint32_t)(wj*16 + nt*8) << 7) + boff + kk*32) ^ xl));
            #pragma unroll
            for (int mt = 0; mt < 2; ++mt)
                #pragma unroll
                for (int nt = 0; nt < 2; ++nt)
                    mma16816(zacc[mt][nt], A[mt], B[nt]);
        }
        named_bar(1 + wi);   // A (per-wi): ring rows for this wi staged

        // ---- gather band from ring; s-transform; S store ----
        {
            int gb = (i0 - 64 * tile + 1023) % 192;
            #pragma unroll
            for (int mt = 0; mt < 2; ++mt)
                #pragma unroll
                for (int nt = 0; nt < 2; ++nt)
                    #pragma unroll
                    for (int r = 0; r < 4; ++r) {
                        int ii = wi*32 + mt*16 + qr + ((r >> 1) << 3);
                        int jj = wj*16 + nt*8 + qc + (r & 1);
                        int slot = gb + ii - jj;
                        if (slot >= 192) slot -= 192;
                        zacc[mt][nt][r] += Pring[ii * RSTR + slot];
                    }
        }
        #pragma unroll
        for (int mt = 0; mt < 2; ++mt)
            #pragma unroll
            for (int nt = 0; nt < 2; ++nt)
                #pragma unroll
                for (int r = 0; r < 4; ++r) {
                    float z = zacc[mt][nt][r];
                    float s = fmaf(z, fmaf(z, 0.5f, 1.f), 1.f);
                    zacc[mt][nt][r] = s;
                    dsum[mt * 2 + (r >> 1)] += s;
                }
        #pragma unroll
        for (int mt = 0; mt < 2; ++mt)
            #pragma unroll
            for (int nt = 0; nt < 2; ++nt) {
                int r0 = wi*32 + mt*16 + qr;
                int c0 = wj*16 + nt*8 + qc;
                uint32_t h0, l0, h1, l1;
                cvt_pair(zacc[mt][nt][0], zacc[mt][nt][1], h0, l0);
                cvt_pair(zacc[mt][nt][2], zacc[mt][nt][3], h1, l1);
                uint32_t off0 = ((uint32_t)(r0 * 128 + c0 * 2)) ^ xs;
                *(uint32_t*)(smc + S_HI + off0) = h0;
                *(uint32_t*)(smc + S_LO + off0) = l0;
                *(uint32_t*)(smc + S_HI + off0 + 1024) = h1;
                *(uint32_t*)(smc + S_LO + off0 + 1024) = l1;
            }
        named_bar(1 + wi);   // B (per-wi): this wi's S rows visible

        // ---- L1 prefetch hints for tile t+1 (zero register cost) ----
        if (tile < NT - 1 && (t & 7) == 0) {
            int row = t >> 4;
            const float* kp = kb + (size_t)(j0 + 64) * 64;
            const float* vp = vb + (size_t)(j0 + 64) * 64;
            int un = i0 + 960 - 64 * (tile + 1);
            pf_l1(kp + (size_t)row * 64 + (t & 15) * 4);
            pf_l1(kp + (size_t)(row + 32) * 64 + (t & 15) * 4);
            pf_l1(vp + (size_t)row * 64 + (t & 15) * 4);
            pf_l1(vp + (size_t)(row + 32) * 64 + (t & 15) * 4);
            int g0 = un + row;      if (g0 > 2046) g0 = 2046;
            int g1 = un + row + 32; if (g1 > 2046) g1 = 2046;
            pf_l1(rpe + (size_t)g0 * 64 + (t & 15) * 4);
            pf_l1(rpe + (size_t)g1 * 64 + (t & 15) * 4);
        }

        // ---- SV MMAs: O += S V (3-split; vB cached) ----
        {
            uint32_t vB[4][2][2];
            #pragma unroll
            for (int kk = 0; kk < 4; ++kk)
                #pragma unroll
                for (int nt = 0; nt < 2; ++nt)
                    ldmBT(vB[kk][nt], sb + V_HI +
                          ((((uint32_t)(kk*16) << 7) + voff +
                            (uint32_t)(wj*32 + nt*16)) ^ xl));
            #pragma unroll
            for (int kk = 0; kk < 4; ++kk) {
                uint32_t A[2][4];
                #pragma unroll
                for (int mt = 0; mt < 2; ++mt)
                    ldmA(A[mt], sb + S_HI +
                         ((((uint32_t)(wi*32 + mt*16) << 7) + aoff + kk*32) ^ xl));
                #pragma unroll
                for (int mt = 0; mt < 2; ++mt)     // S_HI x V_HI
                    #pragma unroll
                    for (int nt = 0; nt < 2; ++nt)
                        mma16816(oacc[mt][nt], A[mt], vB[kk][nt]);
                uint32_t B[2][2];
                #pragma unroll
                for (int nt = 0; nt < 2; ++nt)
                    ldmBT(B[nt], sb + V_LO +
                          ((((uint32_t)(kk*16) << 7) + voff +
                            (uint32_t)(wj*32 + nt*16)) ^ xl));
                #pragma unroll
                for (int mt = 0; mt < 2; ++mt)     // S_HI x V_LO
                    #pragma unroll
                    for (int nt = 0; nt < 2; ++nt)
                        mma16816(oacc[mt][nt], A[mt], B[nt]);
                uint32_t A2[2][4];
                #pragma unroll
                for (int mt = 0; mt < 2; ++mt)
                    ldmA(A2[mt], sb + S_LO +
                         ((((uint32_t)(wi*32 + mt*16) << 7) + aoff + kk*32) ^ xl));
                #pragma unroll
                for (int mt = 0; mt < 2; ++mt)     // S_LO x V_HI
                    #pragma unroll
                    for (int nt = 0; nt < 2; ++nt)
                        mma16816(oacc[mt][nt], A2[mt], vB[kk][nt]);
            }
        }
    }

    // ---- reduce denominators ----
    #pragma unroll
    for (int u = 0; u < 4; ++u) {
        float s = dsum[u];
        s += __shfl_xor_sync(0xffffffffu, s, 1);
        s += __shfl_xor_sync(0xffffffffu, s, 2);
        if ((lane & 3) == 0)
            atomicAdd(&Dsm[wi*32 + (u >> 1)*16 + qr + ((u & 1) << 3)], s);
    }
    __syncthreads();

    // ---- epilogue ----
    #pragma unroll
    for (int mt = 0; mt < 2; ++mt)
        #pragma unroll
        for (int nt = 0; nt < 2; ++nt) {
            int ii = wi*32 + mt*16 + qr;
            int d0 = wj*16 + nt*8 + qc;
            float inv0 = 1.f / Dsm[ii];
            float inv1 = 1.f / Dsm[ii + 8];
            float* o0 = out + ((size_t)(bh * NSEQ + i0 + ii)) * 64 + d0;
            *(float2*)o0 = make_float2(oacc[mt][nt][0] * inv0, oacc[mt][nt][1] * inv0);
            *(float2*)(o0 + 8 * 64) =
                make_float2(oacc[mt][nt][2] * inv1, oacc[mt][nt][3] * inv1);
        }
}

extern "C" void kernel_launch(void* const* d_in, const int* in_sizes, int n_in,
                              void* d_out, int out_size)
{
    const float* q   = (const float*)d_in[0];
    const float* k   = (const float*)d_in[1];
    const float* v   = (const float*)d_in[2];
    // d_in[3] = drop_noise (unused)
    const float* rpe = (const float*)d_in[4];
    float* out = (float*)d_out;

    cudaFuncSetAttribute(fast_attn_hmma,
                         cudaFuncAttributeMaxDynamicSharedMemorySize, SMEM_BYTES);
    dim3 grid(NSEQ / BI, 16);   // 8 x 16 = 128 CTAs, one wave
    fast_attn_hmma<<<grid, 512, SMEM_BYTES>>>(q, k, v, rpe, out);
}